// round 17
// baseline (speedup 1.0000x reference)
#include <cuda_runtime.h>
#include <cuda_fp16.h>

#define B_    4
#define N_    2048
#define F_IN  256
#define H_    8
#define F_OUT 64
#define HF    (H_ * F_OUT)       // 512
#define HG    4                  // heads per agg CTA
#define NHG   (H_ / HG)          // 2 head groups

// Scratch (device globals: allocation-free per harness rules)
__device__ __half g_h16[(size_t)B_ * N_ * HF];     // [b][n][h][o], fp16
__device__ float  g_atts2[B_ * N_ * H_];           // [b][n][h]
__device__ float  g_attn2[B_ * N_ * H_];           // [b][n][h]

__device__ __forceinline__ unsigned f2tf32(float f) {
    unsigned r;
    asm("cvt.rna.tf32.f32 %0, %1;" : "=r"(r) : "f"(f));
    return r;
}

__device__ __forceinline__ unsigned s2u(const void* p) {
    return (unsigned)__cvta_generic_to_shared(p);
}

// -------------------------------------------------------------------------
// Kernel 1: h = X @ W per head via tf32 mma.sync (m16n8k8), fp32 accum.
// (R13 measured-best, unchanged)
// -------------------------------------------------------------------------
__global__ __launch_bounds__(256) void gemm_h_tc(const float* __restrict__ X,
                                                 const float* __restrict__ W,
                                                 const float* __restrict__ a_self,
                                                 const float* __restrict__ a_neigh) {
    const int head = blockIdx.y;
    const int b    = blockIdx.x >> 5;
    const int n0   = (blockIdx.x & 31) * 64;

    __shared__ unsigned Xs[64][36];
    __shared__ unsigned Wsm[32][72];
    __shared__ float    hs[64][66];

    const int t    = threadIdx.x;
    const int lane = t & 31;
    const int warp = t >> 5;
    const int wm   = warp >> 1;
    const int wn   = warp & 1;
    const int g    = lane >> 2;
    const int tg   = lane & 3;

    const float* Xb = X + ((size_t)b * N_ + n0) * F_IN;
    const float* Wh = W + (size_t)head * F_IN * F_OUT;

    float c[4][4] = {};

    for (int k0 = 0; k0 < F_IN; k0 += 32) {
        {
            int row = t >> 2;
            int q   = (t & 3) * 8;
            const float* src = Xb + (size_t)row * F_IN + k0 + q;
            float4 u0 = *(const float4*)src;
            float4 u1 = *(const float4*)(src + 4);
            Xs[row][q + 0] = f2tf32(u0.x); Xs[row][q + 1] = f2tf32(u0.y);
            Xs[row][q + 2] = f2tf32(u0.z); Xs[row][q + 3] = f2tf32(u0.w);
            Xs[row][q + 4] = f2tf32(u1.x); Xs[row][q + 5] = f2tf32(u1.y);
            Xs[row][q + 6] = f2tf32(u1.z); Xs[row][q + 7] = f2tf32(u1.w);
        }
        {
            int r = t >> 3;
            int q = (t & 7) * 8;
            const float* src = Wh + (size_t)(k0 + r) * F_OUT + q;
            float4 u0 = *(const float4*)src;
            float4 u1 = *(const float4*)(src + 4);
            Wsm[r][q + 0] = f2tf32(u0.x); Wsm[r][q + 1] = f2tf32(u0.y);
            Wsm[r][q + 2] = f2tf32(u0.z); Wsm[r][q + 3] = f2tf32(u0.w);
            Wsm[r][q + 4] = f2tf32(u1.x); Wsm[r][q + 5] = f2tf32(u1.y);
            Wsm[r][q + 6] = f2tf32(u1.z); Wsm[r][q + 7] = f2tf32(u1.w);
        }
        __syncthreads();

        #pragma unroll
        for (int ks = 0; ks < 4; ks++) {
            unsigned a0 = Xs[wm * 16 + g][ks * 8 + tg];
            unsigned a1 = Xs[wm * 16 + g + 8][ks * 8 + tg];
            unsigned a2 = Xs[wm * 16 + g][ks * 8 + tg + 4];
            unsigned a3 = Xs[wm * 16 + g + 8][ks * 8 + tg + 4];
            #pragma unroll
            for (int nt = 0; nt < 4; nt++) {
                unsigned b0 = Wsm[ks * 8 + tg][wn * 32 + nt * 8 + g];
                unsigned b1 = Wsm[ks * 8 + tg + 4][wn * 32 + nt * 8 + g];
                asm volatile(
                    "mma.sync.aligned.m16n8k8.row.col.f32.tf32.tf32.f32 "
                    "{%0,%1,%2,%3}, {%4,%5,%6,%7}, {%8,%9}, {%0,%1,%2,%3};"
                    : "+f"(c[nt][0]), "+f"(c[nt][1]), "+f"(c[nt][2]), "+f"(c[nt][3])
                    : "r"(a0), "r"(a1), "r"(a2), "r"(a3), "r"(b0), "r"(b1));
            }
        }
        __syncthreads();
    }

    {
        int row = wm * 16 + g;
        #pragma unroll
        for (int nt = 0; nt < 4; nt++) {
            int col = wn * 32 + nt * 8 + tg * 2;
            hs[row][col]     = c[nt][0];
            hs[row][col + 1] = c[nt][1];
            hs[row + 8][col]     = c[nt][2];
            hs[row + 8][col + 1] = c[nt][3];
        }
    }
    __syncthreads();

    {
        int row = t >> 2;
        int seg = (t & 3) * 16;
        const float* as = a_self  + head * F_OUT + seg;
        const float* an = a_neigh + head * F_OUT + seg;
        float v[16];
        float s = 0.f, nn = 0.f;
        #pragma unroll
        for (int cc = 0; cc < 16; cc++) {
            v[cc] = hs[row][seg + cc];
            s  = fmaf(v[cc], as[cc], s);
            nn = fmaf(v[cc], an[cc], nn);
        }
        s  += __shfl_xor_sync(0xFFFFFFFFu, s, 1);
        s  += __shfl_xor_sync(0xFFFFFFFFu, s, 2);
        nn += __shfl_xor_sync(0xFFFFFFFFu, nn, 1);
        nn += __shfl_xor_sync(0xFFFFFFFFu, nn, 2);
        if ((t & 3) == 0) {
            size_t idx = ((size_t)b * N_ + n0 + row) * H_ + head;
            g_atts2[idx] = s;
            g_attn2[idx] = nn;
        }

        __half2 hh[8];
        #pragma unroll
        for (int i = 0; i < 8; i++) hh[i] = __floats2half2_rn(v[2 * i], v[2 * i + 1]);
        uint4 p0, p1;
        p0.x = *(unsigned*)&hh[0]; p0.y = *(unsigned*)&hh[1];
        p0.z = *(unsigned*)&hh[2]; p0.w = *(unsigned*)&hh[3];
        p1.x = *(unsigned*)&hh[4]; p1.y = *(unsigned*)&hh[5];
        p1.z = *(unsigned*)&hh[6]; p1.w = *(unsigned*)&hh[7];
        __half* dst = g_h16 + ((size_t)b * N_ + n0 + row) * HF + head * F_OUT + seg;
        *(uint4*)dst       = p0;
        *(uint4*)(dst + 8) = p1;
    }
}

// -------------------------------------------------------------------------
// Kernel 2: dense-tile tensor-core aggregation.
// CTA = (b, i-tile of 64, head-group of 4). Loop over 32 j-tiles:
//   stage h j-tile (fp16) + attn logits -> build fp16 weight tile
//   (0 where A==0, exp(lrelu) else; denom accumulated from rounded halves)
//   -> fp16 mma.sync m16n8k16 into fp32 accumulators.
// smem (dynamic, 73728 B):
//   __half h_s[64][264]; __half w_s[4][64][72];
//   float atts_s[64][4]; float attn_s[64][4]; float denom_s[64][4];
// -------------------------------------------------------------------------
extern __shared__ char agg_smem[];

__global__ __launch_bounds__(256, 2) void agg_tc(const float* __restrict__ A,
                                                 float* __restrict__ out) {
    const int b  = blockIdx.x >> 5;
    const int i0 = (blockIdx.x & 31) * 64;
    const int hg = blockIdx.y;

    __half (*h_s)[264]     = (__half(*)[264])agg_smem;
    __half (*w_s)[64][72]  = (__half(*)[64][72])(agg_smem + 33792);
    float  (*atts_s)[4]    = (float(*)[4])(agg_smem + 33792 + 36864);
    float  (*attn_s)[4]    = (float(*)[4])(agg_smem + 33792 + 36864 + 1024);
    float  (*denom_s)[4]   = (float(*)[4])(agg_smem + 33792 + 36864 + 2048);

    const int t    = threadIdx.x;
    const int w    = t >> 5;
    const int l    = t & 31;
    const int g    = l >> 2;
    const int tg   = l & 3;
    const int hh   = w & 3;            // local head for MMA phase
    const int wi   = t >> 2;           // weight-phase row 0..63
    const int jq   = t & 3;            // weight-phase j-quarter

    // stage atts once
    atts_s[t >> 2][t & 3] =
        g_atts2[((size_t)(b * N_) + i0 + (t >> 2)) * H_ + hg * HG + (t & 3)];

    float dsum[4] = {};
    float acc[2][8][4] = {};           // [m-task][n-tile][frag]

    for (int jt = 0; jt < N_ / 64; jt++) {
        const int j0 = jt * 64;

        // ---- stage h j-tile (64 x 256 halves) + attn logits ----
        #pragma unroll
        for (int it = 0; it < 8; it++) {
            int idx = t + it * 256;            // 2048 uint4 total
            int row = idx >> 5;
            int q   = idx & 31;
            *(uint4*)&h_s[row][q * 8] =
                *(const uint4*)(g_h16 + ((size_t)(b * N_) + j0 + row) * HF +
                                hg * (HG * F_OUT) + q * 8);
        }
        if (t < 64)
            *(float4*)attn_s[t] =
                *(const float4*)(g_attn2 + ((size_t)(b * N_) + j0 + t) * H_ + hg * HG);
        __syncthreads();

        // ---- weight tile: thread (wi, jq) handles j = jq*16 .. +15 ----
        {
            const float* Arow = A + ((size_t)(b * N_) + i0 + wi) * N_ + j0 + jq * 16;
            unsigned msk = 0;
            #pragma unroll
            for (int q = 0; q < 4; q++) {
                float4 u = *(const float4*)(Arow + q * 4);
                msk |= (u.x != 0.f ? 1u : 0u) << (4 * q)
                     | (u.y != 0.f ? 1u : 0u) << (4 * q + 1)
                     | (u.z != 0.f ? 1u : 0u) << (4 * q + 2)
                     | (u.w != 0.f ? 1u : 0u) << (4 * q + 3);
            }
            #pragma unroll
            for (int h = 0; h < 4; h++) {
                float ath = atts_s[wi][h];
                unsigned wp[8];
                #pragma unroll
                for (int p = 0; p < 8; p++) {
                    unsigned m2 = (msk >> (2 * p)) & 3u;
                    if (m2) {
                        float x0 = ath + attn_s[jq * 16 + 2 * p][h];
                        float x1 = ath + attn_s[jq * 16 + 2 * p + 1][h];
                        float w0 = (m2 & 1u) ? __expf(fmaxf(x0, 0.2f * x0)) : 0.f;
                        float w1 = (m2 & 2u) ? __expf(fmaxf(x1, 0.2f * x1)) : 0.f;
                        __half2 h2 = __floats2half2_rn(w0, w1);
                        dsum[h] += __low2float(h2) + __high2float(h2);
                        wp[p] = *(unsigned*)&h2;
                    } else {
                        wp[p] = 0u;
                    }
                }
                *(uint4*)&w_s[h][wi][jq * 16]     = make_uint4(wp[0], wp[1], wp[2], wp[3]);
                *(uint4*)&w_s[h][wi][jq * 16 + 8] = make_uint4(wp[4], wp[5], wp[6], wp[7]);
            }
        }
        __syncthreads();

        // ---- MMA: warp w -> head hh=w&3, m-quarters {w>>2, (w>>2)+2} ----
        #pragma unroll
        for (int mt = 0; mt < 2; mt++) {
            const int mrow = ((w >> 2) + mt * 2) * 16;
            #pragma unroll
            for (int ks = 0; ks < 4; ks++) {
                unsigned a0, a1, a2, a3;
                unsigned aaddr = s2u(&w_s[hh][mrow + (l & 15)][ks * 16 + ((l & 16) ? 8 : 0)]);
                asm volatile(
                    "ldmatrix.sync.aligned.m8n8.x4.shared.b16 {%0,%1,%2,%3}, [%4];"
                    : "=r"(a0), "=r"(a1), "=r"(a2), "=r"(a3) : "r"(aaddr));
                #pragma unroll
                for (int nt2 = 0; nt2 < 4; nt2++) {
                    unsigned b0, b1, b2, b3;
                    unsigned baddr = s2u(&h_s[ks * 16 + (l & 15)]
                                             [hh * 64 + nt2 * 16 + ((l & 16) ? 8 : 0)]);
                    asm volatile(
                        "ldmatrix.sync.aligned.m8n8.x4.trans.shared.b16 {%0,%1,%2,%3}, [%4];"
                        : "=r"(b0), "=r"(b1), "=r"(b2), "=r"(b3) : "r"(baddr));
                    asm volatile(
                        "mma.sync.aligned.m16n8k16.row.col.f32.f16.f16.f32 "
                        "{%0,%1,%2,%3}, {%4,%5,%6,%7}, {%8,%9}, {%0,%1,%2,%3};"
                        : "+f"(acc[mt][2 * nt2][0]), "+f"(acc[mt][2 * nt2][1]),
                          "+f"(acc[mt][2 * nt2][2]), "+f"(acc[mt][2 * nt2][3])
                        : "r"(a0), "r"(a1), "r"(a2), "r"(a3), "r"(b0), "r"(b1));
                    asm volatile(
                        "mma.sync.aligned.m16n8k16.row.col.f32.f16.f16.f32 "
                        "{%0,%1,%2,%3}, {%4,%5,%6,%7}, {%8,%9}, {%0,%1,%2,%3};"
                        : "+f"(acc[mt][2 * nt2 + 1][0]), "+f"(acc[mt][2 * nt2 + 1][1]),
                          "+f"(acc[mt][2 * nt2 + 1][2]), "+f"(acc[mt][2 * nt2 + 1][3])
                        : "r"(a0), "r"(a1), "r"(a2), "r"(a3), "r"(b2), "r"(b3));
                }
            }
        }
        __syncthreads();
    }

    // ---- denominators: reduce dsum over the 4 jq lanes (lane bits 0..1) ----
    #pragma unroll
    for (int h = 0; h < 4; h++) {
        dsum[h] += __shfl_xor_sync(0xFFFFFFFFu, dsum[h], 1);
        dsum[h] += __shfl_xor_sync(0xFFFFFFFFu, dsum[h], 2);
    }
    if (jq == 0)
        *(float4*)denom_s[wi] = make_float4(dsum[0], dsum[1], dsum[2], dsum[3]);
    __syncthreads();

    // ---- epilogue: out = relu(acc / denom), concat layout ----
    #pragma unroll
    for (int mt = 0; mt < 2; mt++) {
        const int mrow = ((w >> 2) + mt * 2) * 16;
        #pragma unroll
        for (int half8 = 0; half8 < 2; half8++) {
            int row = mrow + g + half8 * 8;
            float inv = 1.0f / denom_s[row][hh];
            float* orow = out + ((size_t)(b * N_) + i0 + row) * HF + (hg * HG + hh) * F_OUT;
            #pragma unroll
            for (int nt = 0; nt < 8; nt++) {
                float2 v;
                v.x = fmaxf(acc[mt][nt][half8 * 2 + 0] * inv, 0.f);
                v.y = fmaxf(acc[mt][nt][half8 * 2 + 1] * inv, 0.f);
                *(float2*)(orow + nt * 8 + tg * 2) = v;
            }
        }
    }
}

// -------------------------------------------------------------------------
extern "C" void kernel_launch(void* const* d_in, const int* in_sizes, int n_in,
                              void* d_out, int out_size) {
    const float* X       = (const float*)d_in[0];
    const float* A       = (const float*)d_in[1];
    const float* W       = (const float*)d_in[2];
    const float* a_self  = (const float*)d_in[3];
    const float* a_neigh = (const float*)d_in[4];
    float* out = (float*)d_out;

    static int smem_set = 0;
    if (!smem_set) {
        cudaFuncSetAttribute(agg_tc, cudaFuncAttributeMaxDynamicSharedMemorySize, 73728);
        smem_set = 1;
    }

    // 1) h = X @ W per head (tf32 tensor cores) + fused logits + fp16 h store
    gemm_h_tc<<<dim3(32 * B_, H_), 256>>>(X, W, a_self, a_neigh);

    // 2) dense-tile tensor-core masked-softmax aggregation + relu + concat
    agg_tc<<<dim3(32 * B_, NHG), 256, 73728>>>(A, out);
}